// round 16
// baseline (speedup 1.0000x reference)
#include <cuda_runtime.h>
#include <cuda_bf16.h>

// Problem constants (fixed by setup_inputs):
//   x: [B=2, C=3, D=128, H=160, W=160] float32, num_steps = 6
#define BB    2
#define DD    128
#define HH    160
#define WW    160
#define PLANE (DD * HH * WW)          // 3,276,800 voxels per (batch) volume
#define NVOX  (BB * PLANE)

// Interleaved ping-pong scratch: float4 per voxel = (flow_d, flow_h, flow_w, 0).
// Batches processed sequentially so the active set (~105 MB) mostly fits L2.
__device__ float4 g_bufA[NVOX];
__device__ float4 g_bufB[NVOX];

__device__ __forceinline__ int clampi(int v, int lo, int hi) {
    return min(max(v, lo), hi);
}

// ---------------------------------------------------------------------------
// K1: step 1 (one batch): planar x -> interleaved v1. Scale fused (s = 1/64).
// 4 consecutive W voxels/thread; taps are ~identity (sigma=0.125) -> coalesced.
// Measured ~16.5 us in R3.
// ---------------------------------------------------------------------------
__global__ __launch_bounds__(256) void sq_first(const float* __restrict__ sb,
                                                float4* __restrict__ db,
                                                float s) {
    const int W4 = WW / 4;
    int idx = blockIdx.x * blockDim.x + threadIdx.x;   // grid covers DD*HH*W4
    int w4 = idx % W4;
    int t  = idx / W4;
    int h  = t % HH;
    int d  = t / HH;

    const int p = (d * HH + h) * WW + w4 * 4;

    float4 f0 = *reinterpret_cast<const float4*>(sb + p);              // d-flow
    float4 f1 = *reinterpret_cast<const float4*>(sb + p + PLANE);      // h-flow
    float4 f2 = *reinterpret_cast<const float4*>(sb + p + 2 * PLANE);  // w-flow

    f0.x *= s; f0.y *= s; f0.z *= s; f0.w *= s;
    f1.x *= s; f1.y *= s; f1.z *= s; f1.w *= s;
    f2.x *= s; f2.y *= s; f2.z *= s; f2.w *= s;

    float fd[4] = {f0.x, f0.y, f0.z, f0.w};
    float fh[4] = {f1.x, f1.y, f1.z, f1.w};
    float fw[4] = {f2.x, f2.y, f2.z, f2.w};

#pragma unroll
    for (int j = 0; j < 4; ++j) {
        int id = clampi(__float2int_rn((float)d + fd[j]), 0, DD - 1);
        int ih = clampi(__float2int_rn((float)h + fh[j]), 0, HH - 1);
        int iw = clampi(__float2int_rn((float)(w4 * 4 + j) + fw[j]), 0, WW - 1);
        const int q = (id * HH + ih) * WW + iw;
        float gd = s * sb[q];
        float gh = s * sb[q + PLANE];
        float gw = s * sb[q + 2 * PLANE];
        db[p + j] = make_float4(fd[j] + gd, fh[j] + gh, fw[j] + gw, 0.0f);
    }
}

// ---------------------------------------------------------------------------
// K2: fused steps 2+3+4 (one batch): interleaved v1 -> interleaved v4.
//   v2(y) = v1(y)+v1(r1(y)); v3(y) = v2(y)+v2(r2(y)); v4(p) = v3(p)+v3(r3(p)).
// 7 float4 gathers/voxel, all at sigma <= 1 voxel -> high sector sharing.
// 2 voxels/thread, warp-contiguous, level-batched. PLANE = 6400 blk * 512 vox.
// ---------------------------------------------------------------------------
__global__ __launch_bounds__(256) void sq_fuse234(const float4* __restrict__ src,
                                                  float4* __restrict__ dst) {
    const int lane = threadIdx.x & 31;
    const int warp = threadIdx.x >> 5;
    const int base = blockIdx.x * 512 + warp * 64 + lane;  // in [0, PLANE)

    int dv[2], hv[2], wv[2];
    float4 a[2];
#pragma unroll
    for (int k = 0; k < 2; ++k) a[k] = src[base + k * 32];     // v1(p)
#pragma unroll
    for (int k = 0; k < 2; ++k) {
        const int v = base + k * 32;
        wv[k] = v % WW;  int t = v / WW;
        hv[k] = t % HH;  dv[k] = t / HH;
    }

    // ---- level 1: g1 = v1(r1(p)) ----
    int r1d[2], r1h[2], r1w[2];
#pragma unroll
    for (int k = 0; k < 2; ++k) {
        r1d[k] = clampi(__float2int_rn((float)dv[k] + a[k].x), 0, DD - 1);
        r1h[k] = clampi(__float2int_rn((float)hv[k] + a[k].y), 0, HH - 1);
        r1w[k] = clampi(__float2int_rn((float)wv[k] + a[k].z), 0, WW - 1);
    }
    float4 g1[2];
#pragma unroll
    for (int k = 0; k < 2; ++k) g1[k] = src[(r1d[k] * HH + r1h[k]) * WW + r1w[k]];

    // ---- v2(p); level 2: g2 = v1(r2(p)) ----
    float v2d[2], v2h[2], v2w[2];
    int r2d[2], r2h[2], r2w[2];
#pragma unroll
    for (int k = 0; k < 2; ++k) {
        v2d[k] = a[k].x + g1[k].x;
        v2h[k] = a[k].y + g1[k].y;
        v2w[k] = a[k].z + g1[k].z;
        r2d[k] = clampi(__float2int_rn((float)dv[k] + v2d[k]), 0, DD - 1);
        r2h[k] = clampi(__float2int_rn((float)hv[k] + v2h[k]), 0, HH - 1);
        r2w[k] = clampi(__float2int_rn((float)wv[k] + v2w[k]), 0, WW - 1);
    }
    float4 g2[2];
#pragma unroll
    for (int k = 0; k < 2; ++k) g2[k] = src[(r2d[k] * HH + r2h[k]) * WW + r2w[k]];

    // ---- g3 = v1(r1(r2)) ----
    int q3[2];
#pragma unroll
    for (int k = 0; k < 2; ++k) {
        int cd = clampi(__float2int_rn((float)r2d[k] + g2[k].x), 0, DD - 1);
        int ch = clampi(__float2int_rn((float)r2h[k] + g2[k].y), 0, HH - 1);
        int cw = clampi(__float2int_rn((float)r2w[k] + g2[k].z), 0, WW - 1);
        q3[k] = (cd * HH + ch) * WW + cw;
    }
    float4 g3[2];
#pragma unroll
    for (int k = 0; k < 2; ++k) g3[k] = src[q3[k]];

    // ---- v3(p); level 3: g4 = v1(r3(p)) ----
    float v3d[2], v3h[2], v3w[2];
    int r3d[2], r3h[2], r3w[2];
#pragma unroll
    for (int k = 0; k < 2; ++k) {
        float v2r2d = g2[k].x + g3[k].x;      // v2(r2)
        float v2r2h = g2[k].y + g3[k].y;
        float v2r2w = g2[k].z + g3[k].z;
        v3d[k] = v2d[k] + v2r2d;
        v3h[k] = v2h[k] + v2r2h;
        v3w[k] = v2w[k] + v2r2w;
        r3d[k] = clampi(__float2int_rn((float)dv[k] + v3d[k]), 0, DD - 1);
        r3h[k] = clampi(__float2int_rn((float)hv[k] + v3h[k]), 0, HH - 1);
        r3w[k] = clampi(__float2int_rn((float)wv[k] + v3w[k]), 0, WW - 1);
    }
    float4 g4[2];
#pragma unroll
    for (int k = 0; k < 2; ++k) g4[k] = src[(r3d[k] * HH + r3h[k]) * WW + r3w[k]];

    // ---- g5 = v1(r1(r3)) ----
    int q5[2];
#pragma unroll
    for (int k = 0; k < 2; ++k) {
        int ed = clampi(__float2int_rn((float)r3d[k] + g4[k].x), 0, DD - 1);
        int eh = clampi(__float2int_rn((float)r3h[k] + g4[k].y), 0, HH - 1);
        int ew = clampi(__float2int_rn((float)r3w[k] + g4[k].z), 0, WW - 1);
        q5[k] = (ed * HH + eh) * WW + ew;
    }
    float4 g5[2];
#pragma unroll
    for (int k = 0; k < 2; ++k) g5[k] = src[q5[k]];

    // ---- v2(r3); g6 = v1(r2(r3)) ----
    float v2r3d[2], v2r3h[2], v2r3w[2];
    int r23d[2], r23h[2], r23w[2];
#pragma unroll
    for (int k = 0; k < 2; ++k) {
        v2r3d[k] = g4[k].x + g5[k].x;
        v2r3h[k] = g4[k].y + g5[k].y;
        v2r3w[k] = g4[k].z + g5[k].z;
        r23d[k] = clampi(__float2int_rn((float)r3d[k] + v2r3d[k]), 0, DD - 1);
        r23h[k] = clampi(__float2int_rn((float)r3h[k] + v2r3h[k]), 0, HH - 1);
        r23w[k] = clampi(__float2int_rn((float)r3w[k] + v2r3w[k]), 0, WW - 1);
    }
    float4 g6[2];
#pragma unroll
    for (int k = 0; k < 2; ++k) g6[k] = src[(r23d[k] * HH + r23h[k]) * WW + r23w[k]];

    // ---- g7 = v1(r1(r2(r3))) ----
    int q7[2];
#pragma unroll
    for (int k = 0; k < 2; ++k) {
        int fd = clampi(__float2int_rn((float)r23d[k] + g6[k].x), 0, DD - 1);
        int fh = clampi(__float2int_rn((float)r23h[k] + g6[k].y), 0, HH - 1);
        int fw = clampi(__float2int_rn((float)r23w[k] + g6[k].z), 0, WW - 1);
        q7[k] = (fd * HH + fh) * WW + fw;
    }
    float4 g7[2];
#pragma unroll
    for (int k = 0; k < 2; ++k) g7[k] = src[q7[k]];

    // ---- combine: v4(p) = v3(p) + (v2(r3) + v2(r2(r3))) ----
#pragma unroll
    for (int k = 0; k < 2; ++k) {
        float v2r23d = g6[k].x + g7[k].x;
        float v2r23h = g6[k].y + g7[k].y;
        float v2r23w = g6[k].z + g7[k].z;
        float v3r3d = v2r3d[k] + v2r23d;     // v3(r3)
        float v3r3h = v2r3h[k] + v2r23h;
        float v3r3w = v2r3w[k] + v2r23w;
        dst[base + k * 32] = make_float4(v3d[k] + v3r3d,
                                         v3h[k] + v3r3h,
                                         v3w[k] + v3r3w, 0.0f);
    }
}

// ---------------------------------------------------------------------------
// K3: fused steps 5+6 (one batch): interleaved v4 -> planar out v6.
//   v5(y) = v4(y) + v4(q4(y));  v6(p) = v5(p) + v5(q5(p)),
//   with v5(q5) = v4(q5) + v4(q4(q5)) recomputed.
// 4 consecutive-W voxels/thread, coalesced planar stores.
// ---------------------------------------------------------------------------
__global__ __launch_bounds__(256) void sq_fuse56last(const float4* __restrict__ sb,
                                                     float* __restrict__ ob) {
    const int W4 = WW / 4;
    int idx = blockIdx.x * blockDim.x + threadIdx.x;
    int w4 = idx % W4;
    int t  = idx / W4;
    int h  = t % HH;
    int d  = t / HH;

    const int p = (d * HH + h) * WW + w4 * 4;

    float4 a[4];
#pragma unroll
    for (int j = 0; j < 4; ++j) a[j] = sb[p + j];

    int q1[4];
#pragma unroll
    for (int j = 0; j < 4; ++j) {
        const int w = w4 * 4 + j;
        int id = clampi(__float2int_rn((float)d + a[j].x), 0, DD - 1);
        int ih = clampi(__float2int_rn((float)h + a[j].y), 0, HH - 1);
        int iw = clampi(__float2int_rn((float)w + a[j].z), 0, WW - 1);
        q1[j] = (id * HH + ih) * WW + iw;
    }
    float4 g1[4];
#pragma unroll
    for (int j = 0; j < 4; ++j) g1[j] = sb[q1[j]];

    float v5d[4], v5h[4], v5w[4];
    int jd[4], jh[4], jw[4], q2[4];
#pragma unroll
    for (int j = 0; j < 4; ++j) {
        const int w = w4 * 4 + j;
        v5d[j] = a[j].x + g1[j].x;
        v5h[j] = a[j].y + g1[j].y;
        v5w[j] = a[j].z + g1[j].z;
        jd[j] = clampi(__float2int_rn((float)d + v5d[j]), 0, DD - 1);
        jh[j] = clampi(__float2int_rn((float)h + v5h[j]), 0, HH - 1);
        jw[j] = clampi(__float2int_rn((float)w + v5w[j]), 0, WW - 1);
        q2[j] = (jd[j] * HH + jh[j]) * WW + jw[j];
    }
    float4 b[4];
#pragma unroll
    for (int j = 0; j < 4; ++j) b[j] = sb[q2[j]];

    int q3[4];
#pragma unroll
    for (int j = 0; j < 4; ++j) {
        int kd = clampi(__float2int_rn((float)jd[j] + b[j].x), 0, DD - 1);
        int kh = clampi(__float2int_rn((float)jh[j] + b[j].y), 0, HH - 1);
        int kw = clampi(__float2int_rn((float)jw[j] + b[j].z), 0, WW - 1);
        q3[j] = (kd * HH + kh) * WW + kw;
    }
    float4 g2[4];
#pragma unroll
    for (int j = 0; j < 4; ++j) g2[j] = sb[q3[j]];

    float o0[4], o1[4], o2[4];
#pragma unroll
    for (int j = 0; j < 4; ++j) {
        float v5qd = b[j].x + g2[j].x;
        float v5qh = b[j].y + g2[j].y;
        float v5qw = b[j].z + g2[j].z;
        o0[j] = v5d[j] + v5qd;
        o1[j] = v5h[j] + v5qh;
        o2[j] = v5w[j] + v5qw;
    }

    *reinterpret_cast<float4*>(ob + p)             = make_float4(o0[0], o0[1], o0[2], o0[3]);
    *reinterpret_cast<float4*>(ob + p + PLANE)     = make_float4(o1[0], o1[1], o1[2], o1[3]);
    *reinterpret_cast<float4*>(ob + p + 2 * PLANE) = make_float4(o2[0], o2[1], o2[2], o2[3]);
}

extern "C" void kernel_launch(void* const* d_in, const int* in_sizes, int n_in,
                              void* d_out, int out_size) {
    const float* x   = (const float*)d_in[0];
    float*       out = (float*)d_out;

    float4 *A = nullptr, *B = nullptr;
    cudaGetSymbolAddress((void**)&A, g_bufA);
    cudaGetSymbolAddress((void**)&B, g_bufB);

    const int tpb  = 256;
    const int blkQ = (DD * HH * (WW / 4)) / tpb;   // 3200 blocks (4 voxels/thread)
    const int blkM = PLANE / 512;                  // 6400 blocks (2 voxels/thread)

    const float s0 = 1.0f / 64.0f;                 // 1 / 2^num_steps (num_steps = 6)

    // Batch-sequential: keeps the per-batch working set mostly L2-resident.
    for (int b = 0; b < BB; ++b) {
        const float* xb = x   + (size_t)b * 3 * PLANE;
        float*       ob = out + (size_t)b * 3 * PLANE;
        float4*      Ab = A   + (size_t)b * PLANE;
        float4*      Bb = B   + (size_t)b * PLANE;

        sq_first     <<<blkQ, tpb>>>(xb, Ab, s0);  // step 1:      x  -> v1
        sq_fuse234   <<<blkM, tpb>>>(Ab, Bb);      // steps 2+3+4: v1 -> v4
        sq_fuse56last<<<blkQ, tpb>>>(Bb, ob);      // steps 5+6:   v4 -> out
    }
}

// round 17
// speedup vs baseline: 1.1543x; 1.1543x over previous
#include <cuda_runtime.h>
#include <cuda_bf16.h>

// Problem constants (fixed by setup_inputs):
//   x: [B=2, C=3, D=128, H=160, W=160] float32, num_steps = 6
#define BB    2
#define DD    128
#define HH    160
#define WW    160
#define PLANE (DD * HH * WW)          // 3,276,800 voxels per (batch) volume
#define NVOX  (BB * PLANE)

// Interleaved ping-pong scratch: float4 per voxel = (flow_d, flow_h, flow_w, 0).
// Batches processed sequentially so the active set (~105 MB) mostly fits L2.
__device__ float4 g_bufA[NVOX];
__device__ float4 g_bufB[NVOX];

__device__ __forceinline__ int clampi(int v, int lo, int hi) {
    return min(max(v, lo), hi);
}

// ---------------------------------------------------------------------------
// K1: fused steps 1+2 (one batch): planar x -> interleaved v2.
//   v0(y) = s*x(y); v1(y) = v0(y) + v0(q0(y)); v2(p) = v1(p) + v1(q1(p)).
// FAST PATHS: v0 has sigma = 0.125 voxels, so round(v0) == 0 with
// P = 1 - 6.3e-5 per component. Level A (q0(p)==p) and level C
// (q0(q1)==q1) are warp-uniformly identity ~99% of the time; in that case
// v1 = v0 + v0 (operands already in registers, bitwise-identical result)
// and 12 scalar loads per thread per level are skipped.
// ---------------------------------------------------------------------------
__global__ __launch_bounds__(256) void sq_fuse12(const float* __restrict__ xb,
                                                 float4* __restrict__ db,
                                                 float s) {
    const int W4 = WW / 4;
    int idx = blockIdx.x * blockDim.x + threadIdx.x;   // grid covers DD*HH*W4
    int w4 = idx % W4;
    int t  = idx / W4;
    int h  = t % HH;
    int d  = t / HH;

    const int p = (d * HH + h) * WW + w4 * 4;

    float4 f0 = *reinterpret_cast<const float4*>(xb + p);              // d-flow
    float4 f1 = *reinterpret_cast<const float4*>(xb + p + PLANE);      // h-flow
    float4 f2 = *reinterpret_cast<const float4*>(xb + p + 2 * PLANE);  // w-flow

    float v0d[4] = {s * f0.x, s * f0.y, s * f0.z, s * f0.w};
    float v0h[4] = {s * f1.x, s * f1.y, s * f1.z, s * f1.w};
    float v0w[4] = {s * f2.x, s * f2.y, s * f2.z, s * f2.w};

    // ---- level A: q0(p); identity test ----
    int ad[4], ah[4], aw[4];
    bool idA = true;
#pragma unroll
    for (int j = 0; j < 4; ++j) {
        const int w = w4 * 4 + j;
        ad[j] = clampi(__float2int_rn((float)d + v0d[j]), 0, DD - 1);
        ah[j] = clampi(__float2int_rn((float)h + v0h[j]), 0, HH - 1);
        aw[j] = clampi(__float2int_rn((float)w + v0w[j]), 0, WW - 1);
        idA = idA && (ad[j] == d) && (ah[j] == h) && (aw[j] == w);
    }

    float v1pd[4], v1ph[4], v1pw[4];
    if (__all_sync(0xFFFFFFFFu, idA)) {
        // q0(p) == p: v0(q0) == v0(p), already in registers.
#pragma unroll
        for (int j = 0; j < 4; ++j) {
            v1pd[j] = v0d[j] + v0d[j];
            v1ph[j] = v0h[j] + v0h[j];
            v1pw[j] = v0w[j] + v0w[j];
        }
    } else {
#pragma unroll
        for (int j = 0; j < 4; ++j) {
            const int qa = (ad[j] * HH + ah[j]) * WW + aw[j];
            v1pd[j] = v0d[j] + s * xb[qa];
            v1ph[j] = v0h[j] + s * xb[qa + PLANE];
            v1pw[j] = v0w[j] + s * xb[qa + 2 * PLANE];
        }
    }

    // ---- level B: q1(p) = clamp(rn(p + v1(p)))  (cannot skip: sigma=0.25) ----
    int bd[4], bh[4], bw[4], qb[4];
#pragma unroll
    for (int j = 0; j < 4; ++j) {
        const int w = w4 * 4 + j;
        bd[j] = clampi(__float2int_rn((float)d + v1pd[j]), 0, DD - 1);
        bh[j] = clampi(__float2int_rn((float)h + v1ph[j]), 0, HH - 1);
        bw[j] = clampi(__float2int_rn((float)w + v1pw[j]), 0, WW - 1);
        qb[j] = (bd[j] * HH + bh[j]) * WW + bw[j];
    }
    float u0d[4], u0h[4], u0w[4];
#pragma unroll
    for (int j = 0; j < 4; ++j) {
        u0d[j] = s * xb[qb[j]];
        u0h[j] = s * xb[qb[j] + PLANE];
        u0w[j] = s * xb[qb[j] + 2 * PLANE];
    }

    // ---- level C: q0(q1) vs q1; identity test ----
    int cd[4], ch[4], cw[4];
    bool idC = true;
#pragma unroll
    for (int j = 0; j < 4; ++j) {
        cd[j] = clampi(__float2int_rn((float)bd[j] + u0d[j]), 0, DD - 1);
        ch[j] = clampi(__float2int_rn((float)bh[j] + u0h[j]), 0, HH - 1);
        cw[j] = clampi(__float2int_rn((float)bw[j] + u0w[j]), 0, WW - 1);
        idC = idC && (cd[j] == bd[j]) && (ch[j] == bh[j]) && (cw[j] == bw[j]);
    }

    float v1qd[4], v1qh[4], v1qw[4];
    if (__all_sync(0xFFFFFFFFu, idC)) {
        // q0(q1) == q1: v0(q0(q1)) == v0(q1) == u0, already in registers.
#pragma unroll
        for (int j = 0; j < 4; ++j) {
            v1qd[j] = u0d[j] + u0d[j];
            v1qh[j] = u0h[j] + u0h[j];
            v1qw[j] = u0w[j] + u0w[j];
        }
    } else {
#pragma unroll
        for (int j = 0; j < 4; ++j) {
            const int qc = (cd[j] * HH + ch[j]) * WW + cw[j];
            v1qd[j] = u0d[j] + s * xb[qc];
            v1qh[j] = u0h[j] + s * xb[qc + PLANE];
            v1qw[j] = u0w[j] + s * xb[qc + 2 * PLANE];
        }
    }

    // ---- v2(p) = v1(p) + v1(q1) ----
#pragma unroll
    for (int j = 0; j < 4; ++j) {
        db[p + j] = make_float4(v1pd[j] + v1qd[j],
                                v1ph[j] + v1qh[j],
                                v1pw[j] + v1qw[j], 0.0f);
    }
}

// ---------------------------------------------------------------------------
// K2: fused steps 3+4 (one batch): interleaved v2 -> interleaved v4.
//   v3(y) = v2(y) + v2(q2(y));  v4(p) = v3(p) + v3(q3(p)),
//   with v3(q3) = v2(q3) + v2(q2(q3)) recomputed.
// 2 voxels/thread, warp-contiguous. PLANE = 6400 blocks * 512 voxels.
// ---------------------------------------------------------------------------
__global__ __launch_bounds__(256) void sq_fuse34(const float4* __restrict__ src,
                                                 float4* __restrict__ dst) {
    const int lane = threadIdx.x & 31;
    const int warp = threadIdx.x >> 5;
    const int vA = blockIdx.x * 512 + warp * 64 + lane;   // in [0, PLANE)

#pragma unroll
    for (int k = 0; k < 2; ++k) {
        const int v = vA + k * 32;
        int w = v % WW;  int t = v / WW;
        int h = t % HH;  int d = t / HH;

        float4 a = src[v];                                  // v2(p)

        int id = clampi(__float2int_rn((float)d + a.x), 0, DD - 1);
        int ih = clampi(__float2int_rn((float)h + a.y), 0, HH - 1);
        int iw = clampi(__float2int_rn((float)w + a.z), 0, WW - 1);
        float4 g1 = src[(id * HH + ih) * WW + iw];          // v2(q2)

        float v3pd = a.x + g1.x;                            // v3(p)
        float v3ph = a.y + g1.y;
        float v3pw = a.z + g1.z;

        int jd = clampi(__float2int_rn((float)d + v3pd), 0, DD - 1);
        int jh = clampi(__float2int_rn((float)h + v3ph), 0, HH - 1);
        int jw = clampi(__float2int_rn((float)w + v3pw), 0, WW - 1);
        float4 b = src[(jd * HH + jh) * WW + jw];           // v2(q3)

        int kd = clampi(__float2int_rn((float)jd + b.x), 0, DD - 1);
        int kh = clampi(__float2int_rn((float)jh + b.y), 0, HH - 1);
        int kw = clampi(__float2int_rn((float)jw + b.z), 0, WW - 1);
        float4 g2 = src[(kd * HH + kh) * WW + kw];          // v2(q2(q3))

        float v3qd = b.x + g2.x;                            // v3(q3)
        float v3qh = b.y + g2.y;
        float v3qw = b.z + g2.z;

        dst[v] = make_float4(v3pd + v3qd, v3ph + v3qh, v3pw + v3qw, 0.0f);
    }
}

// ---------------------------------------------------------------------------
// K3: fused steps 5+6 (one batch): interleaved v4 -> planar out v6.
//   v5(y) = v4(y) + v4(q4(y));  v6(p) = v5(p) + v5(q5(p)),
//   with v5(q5) = v4(q5) + v4(q4(q5)) recomputed.
// 4 consecutive-W voxels/thread for coalesced planar per-channel stores.
// ---------------------------------------------------------------------------
__global__ __launch_bounds__(256) void sq_fuse56last(const float4* __restrict__ sb,
                                                     float* __restrict__ ob) {
    const int W4 = WW / 4;
    int idx = blockIdx.x * blockDim.x + threadIdx.x;
    int w4 = idx % W4;
    int t  = idx / W4;
    int h  = t % HH;
    int d  = t / HH;

    const int p = (d * HH + h) * WW + w4 * 4;

    float o0[4], o1[4], o2[4];
#pragma unroll
    for (int j = 0; j < 4; ++j) {
        const int w = w4 * 4 + j;
        float4 a = sb[p + j];                               // v4(p)

        int id = clampi(__float2int_rn((float)d + a.x), 0, DD - 1);
        int ih = clampi(__float2int_rn((float)h + a.y), 0, HH - 1);
        int iw = clampi(__float2int_rn((float)w + a.z), 0, WW - 1);
        float4 g1 = sb[(id * HH + ih) * WW + iw];           // v4(q4)

        float v5pd = a.x + g1.x;                            // v5(p)
        float v5ph = a.y + g1.y;
        float v5pw = a.z + g1.z;

        int jd = clampi(__float2int_rn((float)d + v5pd), 0, DD - 1);
        int jh = clampi(__float2int_rn((float)h + v5ph), 0, HH - 1);
        int jw = clampi(__float2int_rn((float)w + v5pw), 0, WW - 1);
        float4 b = sb[(jd * HH + jh) * WW + jw];            // v4(q5)

        int kd = clampi(__float2int_rn((float)jd + b.x), 0, DD - 1);
        int kh = clampi(__float2int_rn((float)jh + b.y), 0, HH - 1);
        int kw = clampi(__float2int_rn((float)jw + b.z), 0, WW - 1);
        float4 g2 = sb[(kd * HH + kh) * WW + kw];           // v4(q4(q5))

        float v5qd = b.x + g2.x;                            // v5(q5)
        float v5qh = b.y + g2.y;
        float v5qw = b.z + g2.z;

        o0[j] = v5pd + v5qd;                                // v6(p)
        o1[j] = v5ph + v5qh;
        o2[j] = v5pw + v5qw;
    }

    *reinterpret_cast<float4*>(ob + p)             = make_float4(o0[0], o0[1], o0[2], o0[3]);
    *reinterpret_cast<float4*>(ob + p + PLANE)     = make_float4(o1[0], o1[1], o1[2], o1[3]);
    *reinterpret_cast<float4*>(ob + p + 2 * PLANE) = make_float4(o2[0], o2[1], o2[2], o2[3]);
}

extern "C" void kernel_launch(void* const* d_in, const int* in_sizes, int n_in,
                              void* d_out, int out_size) {
    const float* x   = (const float*)d_in[0];
    float*       out = (float*)d_out;

    float4 *A = nullptr, *B = nullptr;
    cudaGetSymbolAddress((void**)&A, g_bufA);
    cudaGetSymbolAddress((void**)&B, g_bufB);

    const int tpb  = 256;
    const int blkQ = (DD * HH * (WW / 4)) / tpb;   // 3200 blocks (4 voxels/thread)
    const int blkM = PLANE / 512;                  // 6400 blocks (2 voxels/thread)

    const float s0 = 1.0f / 64.0f;                 // 1 / 2^num_steps (num_steps = 6)

    // Batch-sequential: keeps the per-batch working set mostly L2-resident.
    for (int b = 0; b < BB; ++b) {
        const float* xb = x   + (size_t)b * 3 * PLANE;
        float*       ob = out + (size_t)b * 3 * PLANE;
        float4*      Ab = A   + (size_t)b * PLANE;
        float4*      Bb = B   + (size_t)b * PLANE;

        sq_fuse12    <<<blkQ, tpb>>>(xb, Ab, s0);  // steps 1+2: x  -> v2
        sq_fuse34    <<<blkM, tpb>>>(Ab, Bb);      // steps 3+4: v2 -> v4
        sq_fuse56last<<<blkQ, tpb>>>(Bb, ob);      // steps 5+6: v4 -> out
    }
}